// round 13
// baseline (speedup 1.0000x reference)
#include <cuda_runtime.h>
#include <cuda_bf16.h>
#include <cstdint>

// RotationComponent: w_rotated = w @ rot, a_rotated = x @ rot, rot a
// normalized randomized Hadamard: rot[i,j] = H[i,j] * rot[0,j], H Sylvester,
// rot[0,j] = s_j * 2^-6 exactly (s_j = +-1, 2^-6 exact in fp32). Hence
//   (v @ rot)[j] = FWHT(v)[j] * s_j * 2^-6.
//
// SINGLE launch. One CTA per row. CTA 0 additionally packs the per-threadIdx
// sign-mask table (masks depend only on threadIdx: thread t owns columns
// i = c*1024 + t*4 + e in every CTA) and publishes it via threadfence + flag.
// Other CTAs poll the flag once (thread 0) inside the TMA-load shadow. On
// graph replays the flag is already set and CTA 0 rewrites g_mask with
// bit-identical values (benign same-value race); per-launch work is identical.
//
//   - input row via ONE cp.async.bulk (TMA) 16KB copy + mbarrier
//   - epilogue = sign-XOR + exact 2^-6 multiply, 4x STG.128
//   - __launch_bounds__(256, 8): 8 CTAs/SM
//
// FWHT phases (shuffle-free, conflict-free swizzled smem):
//   P1: regs = i-bits {9..6}   i = (t>>6)*1024 + r*64 + (t&63)
//   P2: regs = i-bits {5..2}   i = J*64 + r*4 + e2
//   P3: regs = i-bits {11,10,1,0} -> 4 aligned float4, STG.128
// Swizzle: phys = i ^ ((i>>4) & 28) (16B-granular, preserves LDS.128 blocks).

#define DIM 4096
#define W_ROWS 4096
#define THREADS 256
#define ROW_BYTES (DIM * 4)
#define INV64 0.015625f

__device__ unsigned g_mask[THREADS];       // per-threadIdx sign masks (1 KB)
__device__ volatile unsigned g_flag;       // 0 at module load; set by CTA 0

__device__ __forceinline__ int swz(int i)
{
    return i ^ ((i >> 4) & 28);
}

__device__ __forceinline__ uint32_t smem_u32(const void* p)
{
    uint32_t a;
    asm("{ .reg .u64 t; cvta.to.shared.u64 t, %1; cvt.u32.u64 %0, t; }"
        : "=r"(a) : "l"(p));
    return a;
}

__global__ __launch_bounds__(THREADS, 8)
void fwht_rotate_kernel(const float* __restrict__ w,
                        const float* __restrict__ x,
                        const float* __restrict__ rot,
                        float* __restrict__ out)
{
    __shared__ float buf[DIM];
    __shared__ __align__(8) unsigned long long mbar;

    const int row  = blockIdx.x;
    const int t    = threadIdx.x;
    const int lane = t & 31;
    const int warp = t >> 5;

    const float* src = (row < W_ROWS)
        ? (w + (size_t)row * DIM)
        : (x + (size_t)(row - W_ROWS) * DIM);

    const uint32_t mb = smem_u32(&mbar);

    // ---- Kick off TMA bulk load ASAP (t0 path self-ordered) ----
    if (t == 0) {
        asm volatile("mbarrier.init.shared.b64 [%0], 1;" :: "r"(mb) : "memory");
        asm volatile("fence.proxy.async.shared::cta;" ::: "memory");
        asm volatile("mbarrier.arrive.expect_tx.shared.b64 _, [%0], %1;"
                     :: "r"(mb), "r"((uint32_t)ROW_BYTES) : "memory");
        asm volatile("cp.async.bulk.shared::cta.global.mbarrier::complete_tx::bytes "
                     "[%0], [%1], %2, [%3];"
                     :: "r"(smem_u32(buf)), "l"(src),
                        "r"((uint32_t)ROW_BYTES), "r"(mb)
                     : "memory");
    }

    // ---- Sign mask acquisition (overlaps TMA latency) ----
    unsigned mask;
    if (row == 0) {
        // CTA 0: pack own mask from rot row 0 and publish the table.
        mask = 0;
        #pragma unroll
        for (int c = 0; c < 4; c++) {
            float4 s = __ldg((const float4*)(rot + c * 1024 + t * 4));
            mask |= (__float_as_uint(s.x) >> 31) << (c * 4 + 0);
            mask |= (__float_as_uint(s.y) >> 31) << (c * 4 + 1);
            mask |= (__float_as_uint(s.z) >> 31) << (c * 4 + 2);
            mask |= (__float_as_uint(s.w) >> 31) << (c * 4 + 3);
        }
        g_mask[t] = mask;
        __threadfence();
        __syncthreads();          // all 256 mask stores fenced before flag
        if (t == 0) g_flag = 1;
    } else {
        if (t == 0) {
            while (g_flag == 0) { }   // spins only on the very first run
            __threadfence();          // acquire: order g_mask reads after flag
        }
        __syncthreads();              // also covers mbarrier-init visibility
        mask = g_mask[t];
    }

    // ---- Barrier-init visibility for CTA 0 path + wait for TMA ----
    __syncthreads();
    asm volatile(
        "{\n\t"
        ".reg .pred P1;\n\t"
        "WAIT_LOOP_%=:\n\t"
        "mbarrier.try_wait.parity.acquire.cta.shared::cta.b64 P1, [%0], 0, 0x989680;\n\t"
        "@P1 bra.uni WAIT_DONE_%=;\n\t"
        "bra.uni WAIT_LOOP_%=;\n\t"
        "WAIT_DONE_%=:\n\t"
        "}"
        :: "r"(mb) : "memory");

    float v[16];

    // ---- P1: linear smem read; butterflies on i-bits {9..6} ----
    const int p1_base = (t >> 6) * 1024 + (t & 63);
    #pragma unroll
    for (int r = 0; r < 16; r++) {
        v[r] = buf[p1_base + r * 64];
    }
    #pragma unroll
    for (int m = 8; m >= 1; m >>= 1) {
        #pragma unroll
        for (int r = 0; r < 16; r++) {
            if ((r & m) == 0) {
                float a = v[r], b = v[r | m];
                v[r]     = a + b;
                v[r | m] = a - b;
            }
        }
    }
    __syncthreads();   // in-place reuse: all P1 reads done

    // ---- T1: swizzled write (conflict-free) ----
    #pragma unroll
    for (int r = 0; r < 16; r++) {
        buf[swz(p1_base + r * 64)] = v[r];
    }
    __syncthreads();

    // ---- P2: butterflies on i-bits {5..2} ----
    const int p2_base = (warp * 8 + ((lane >> 2) & 7)) * 64 + (lane & 3);
    #pragma unroll
    for (int r = 0; r < 16; r++) {
        v[r] = buf[swz(p2_base + r * 4)];
    }
    #pragma unroll
    for (int m = 8; m >= 1; m >>= 1) {
        #pragma unroll
        for (int r = 0; r < 16; r++) {
            if ((r & m) == 0) {
                float a = v[r], b = v[r | m];
                v[r]     = a + b;
                v[r | m] = a - b;
            }
        }
    }
    #pragma unroll
    for (int r = 0; r < 16; r++) {
        buf[swz(p2_base + r * 4)] = v[r];
    }
    __syncthreads();

    // ---- P3: LDS.128; butterflies on i-bits {11,10,1,0} ----
    const int p3_base = t * 4;
    #pragma unroll
    for (int c = 0; c < 4; c++) {
        float4 q = *(const float4*)(buf + swz(c * 1024 + p3_base));
        v[c * 4 + 0] = q.x;
        v[c * 4 + 1] = q.y;
        v[c * 4 + 2] = q.z;
        v[c * 4 + 3] = q.w;
    }
    #pragma unroll
    for (int m = 8; m >= 1; m >>= 1) {
        #pragma unroll
        for (int r = 0; r < 16; r++) {
            if ((r & m) == 0) {
                float a = v[r], b = v[r | m];
                v[r]     = a + b;
                v[r | m] = a - b;
            }
        }
    }

    // ---- Epilogue: sign-XOR + exact 2^-6 scale, 4x STG.128 ----
    float* dst = out + (size_t)row * DIM;
    #pragma unroll
    for (int c = 0; c < 4; c++) {
        float4 o;
        #pragma unroll
        for (int e = 0; e < 4; e++) {
            const int k = c * 4 + e;
            const unsigned sb = (mask >> k) << 31;
            ((float*)&o)[e] =
                __int_as_float(__float_as_int(v[k]) ^ (int)sb) * INV64;
        }
        *(float4*)(dst + c * 1024 + p3_base) = o;
    }
}

extern "C" void kernel_launch(void* const* d_in, const int* in_sizes, int n_in,
                              void* d_out, int out_size)
{
    const float* w   = (const float*)d_in[0];   // [4096, 4096]
    const float* x   = (const float*)d_in[1];   // [4, 2048, 4096]
    const float* rot = (const float*)d_in[2];   // [4096, 4096]
    float* out = (float*)d_out;                 // w_rotated then a_rotated

    (void)in_sizes; (void)n_in; (void)out_size;

    fwht_rotate_kernel<<<12288, THREADS>>>(w, x, rot, out);
}

// round 14
// speedup vs baseline: 1.1140x; 1.1140x over previous
#include <cuda_runtime.h>
#include <cuda_bf16.h>
#include <cstdint>

// RotationComponent: w_rotated = w @ rot, a_rotated = x @ rot, rot a
// normalized randomized Hadamard: rot[i,j] = H[i,j] * rot[0,j], H the
// 4096x4096 Sylvester Hadamard (symmetric, H[0,:] = +1). Hence
//   (v @ rot)[j] = FWHT(v)[j] * rot[0,j]
// with per-column scales read directly from rot's first row (exact).
//
// SINGLE launch, one CTA per row. Input row via ONE cp.async.bulk (TMA) 16KB
// copy + mbarrier (no per-warp LDG burst -> no L1tex-queue contention at high
// occupancy). Epilogue multiplies by rot[0,j] float4s (L1-hit; instruction-
// minimal: the 16 FMULs are mandatory in any variant, and this avoids all
// sign-packing ALU, mask launches, and flag fences).
// __launch_bounds__(256, 8): 32 regs -> 8 CTAs/SM (R12 proves no spills).
//
// FWHT phases (shuffle-free, conflict-free swizzled smem):
//   P1: regs = i-bits {9..6}   i = (t>>6)*1024 + r*64 + (t&63)
//   P2: regs = i-bits {5..2}   i = J*64 + r*4 + e2
//   P3: regs = i-bits {11,10,1,0} -> 4 aligned float4, STG.128
// Swizzle: phys = i ^ ((i>>4) & 28) (16B-granular, preserves LDS.128 blocks).

#define DIM 4096
#define W_ROWS 4096
#define THREADS 256
#define ROW_BYTES (DIM * 4)

__device__ __forceinline__ int swz(int i)
{
    return i ^ ((i >> 4) & 28);
}

__device__ __forceinline__ uint32_t smem_u32(const void* p)
{
    uint32_t a;
    asm("{ .reg .u64 t; cvta.to.shared.u64 t, %1; cvt.u32.u64 %0, t; }"
        : "=r"(a) : "l"(p));
    return a;
}

__global__ __launch_bounds__(THREADS, 8)
void fwht_rotate_kernel(const float* __restrict__ w,
                        const float* __restrict__ x,
                        const float* __restrict__ rot,
                        float* __restrict__ out)
{
    __shared__ float buf[DIM];
    __shared__ __align__(8) unsigned long long mbar;

    const int row  = blockIdx.x;
    const int t    = threadIdx.x;
    const int lane = t & 31;
    const int warp = t >> 5;

    const float* src = (row < W_ROWS)
        ? (w + (size_t)row * DIM)
        : (x + (size_t)(row - W_ROWS) * DIM);

    const uint32_t mb = smem_u32(&mbar);

    // ---- Kick off TMA bulk load ASAP (t0 path self-ordered) ----
    if (t == 0) {
        asm volatile("mbarrier.init.shared.b64 [%0], 1;" :: "r"(mb) : "memory");
        asm volatile("fence.proxy.async.shared::cta;" ::: "memory");
        asm volatile("mbarrier.arrive.expect_tx.shared.b64 _, [%0], %1;"
                     :: "r"(mb), "r"((uint32_t)ROW_BYTES) : "memory");
        asm volatile("cp.async.bulk.shared::cta.global.mbarrier::complete_tx::bytes "
                     "[%0], [%1], %2, [%3];"
                     :: "r"(smem_u32(buf)), "l"(src),
                        "r"((uint32_t)ROW_BYTES), "r"(mb)
                     : "memory");
    }

    // ---- Barrier-init visibility, then wait for TMA (parity 0, HW sleep) ----
    __syncthreads();
    asm volatile(
        "{\n\t"
        ".reg .pred P1;\n\t"
        "WAIT_LOOP_%=:\n\t"
        "mbarrier.try_wait.parity.acquire.cta.shared::cta.b64 P1, [%0], 0, 0x989680;\n\t"
        "@P1 bra.uni WAIT_DONE_%=;\n\t"
        "bra.uni WAIT_LOOP_%=;\n\t"
        "WAIT_DONE_%=:\n\t"
        "}"
        :: "r"(mb) : "memory");

    float v[16];

    // ---- P1: linear smem read; butterflies on i-bits {9..6} ----
    const int p1_base = (t >> 6) * 1024 + (t & 63);
    #pragma unroll
    for (int r = 0; r < 16; r++) {
        v[r] = buf[p1_base + r * 64];
    }
    #pragma unroll
    for (int m = 8; m >= 1; m >>= 1) {
        #pragma unroll
        for (int r = 0; r < 16; r++) {
            if ((r & m) == 0) {
                float a = v[r], b = v[r | m];
                v[r]     = a + b;
                v[r | m] = a - b;
            }
        }
    }
    __syncthreads();   // in-place reuse: all P1 reads done

    // ---- T1: swizzled write (conflict-free) ----
    #pragma unroll
    for (int r = 0; r < 16; r++) {
        buf[swz(p1_base + r * 64)] = v[r];
    }
    __syncthreads();

    // ---- P2: butterflies on i-bits {5..2} ----
    const int p2_base = (warp * 8 + ((lane >> 2) & 7)) * 64 + (lane & 3);
    #pragma unroll
    for (int r = 0; r < 16; r++) {
        v[r] = buf[swz(p2_base + r * 4)];
    }
    #pragma unroll
    for (int m = 8; m >= 1; m >>= 1) {
        #pragma unroll
        for (int r = 0; r < 16; r++) {
            if ((r & m) == 0) {
                float a = v[r], b = v[r | m];
                v[r]     = a + b;
                v[r | m] = a - b;
            }
        }
    }
    #pragma unroll
    for (int r = 0; r < 16; r++) {
        buf[swz(p2_base + r * 4)] = v[r];
    }
    __syncthreads();

    // ---- P3: LDS.128; butterflies on i-bits {11,10,1,0} ----
    const int p3_base = t * 4;
    #pragma unroll
    for (int c = 0; c < 4; c++) {
        float4 q = *(const float4*)(buf + swz(c * 1024 + p3_base));
        v[c * 4 + 0] = q.x;
        v[c * 4 + 1] = q.y;
        v[c * 4 + 2] = q.z;
        v[c * 4 + 3] = q.w;
    }
    #pragma unroll
    for (int m = 8; m >= 1; m >>= 1) {
        #pragma unroll
        for (int r = 0; r < 16; r++) {
            if ((r & m) == 0) {
                float a = v[r], b = v[r | m];
                v[r]     = a + b;
                v[r | m] = a - b;
            }
        }
    }

    // ---- Epilogue: scale by rot[0, i] (LDG.128, L1-hit), 4x STG.128 ----
    float* dst = out + (size_t)row * DIM;
    #pragma unroll
    for (int c = 0; c < 4; c++) {
        const int idx = c * 1024 + p3_base;
        float4 s = __ldg((const float4*)(rot + idx));
        float4 o;
        o.x = v[c * 4 + 0] * s.x;
        o.y = v[c * 4 + 1] * s.y;
        o.z = v[c * 4 + 2] * s.z;
        o.w = v[c * 4 + 3] * s.w;
        *(float4*)(dst + idx) = o;
    }
}

extern "C" void kernel_launch(void* const* d_in, const int* in_sizes, int n_in,
                              void* d_out, int out_size)
{
    const float* w   = (const float*)d_in[0];   // [4096, 4096]
    const float* x   = (const float*)d_in[1];   // [4, 2048, 4096]
    const float* rot = (const float*)d_in[2];   // [4096, 4096]
    float* out = (float*)d_out;                 // w_rotated then a_rotated

    (void)in_sizes; (void)n_in; (void)out_size;

    fwht_rotate_kernel<<<12288, THREADS>>>(w, x, rot, out);
}

// round 15
// speedup vs baseline: 1.2115x; 1.0875x over previous
#include <cuda_runtime.h>
#include <cuda_bf16.h>
#include <cstdint>

// RotationComponent: w_rotated = w @ rot, a_rotated = x @ rot, rot a
// normalized randomized Hadamard: rot[i,j] = H[i,j] * rot[0,j], H Sylvester,
// rot[0,j] = s_j * 2^-6 exactly (s_j = +-1, 2^-6 exact in fp32). Hence
//   (v @ rot)[j] = FWHT(v)[j] * s_j * 2^-6.
//
// SINGLE launch, TWO rows per CTA (grid 6144; rows bid and bid+6144), each in
// its own 16KB smem buffer, both TMA bulk loads issued back-to-back in the
// prologue -> row B's load latency fully hidden behind row A's compute, and
// per-CTA fixed costs (mask pack, prologue) amortize over 2 rows.
// Sign mask (depends only on threadIdx) packed from 4 rot float4 loads in the
// prologue, overlapped with the TMA wait; epilogue = XOR + exact 2^-6 mul.
//
// FWHT phases (shuffle-free, conflict-free swizzled smem):
//   P1: regs = i-bits {9..6}   i = (t>>6)*1024 + r*64 + (t&63)
//   P2: regs = i-bits {5..2}   i = J*64 + r*4 + e2
//   P3: regs = i-bits {11,10,1,0} -> 4 aligned float4, STG.128
// Swizzle: phys = i ^ ((i>>4) & 28) (16B-granular, preserves LDS.128 blocks).

#define DIM 4096
#define W_ROWS 4096
#define THREADS 256
#define GRID 6144
#define ROW_BYTES (DIM * 4)
#define INV64 0.015625f

__device__ __forceinline__ int swz(int i)
{
    return i ^ ((i >> 4) & 28);
}

__device__ __forceinline__ uint32_t smem_u32(const void* p)
{
    uint32_t a;
    asm("{ .reg .u64 t; cvta.to.shared.u64 t, %1; cvt.u32.u64 %0, t; }"
        : "=r"(a) : "l"(p));
    return a;
}

__device__ __forceinline__ void mbar_wait0(uint32_t mb)
{
    asm volatile(
        "{\n\t"
        ".reg .pred P1;\n\t"
        "WAIT_LOOP_%=:\n\t"
        "mbarrier.try_wait.parity.acquire.cta.shared::cta.b64 P1, [%0], 0, 0x989680;\n\t"
        "@P1 bra.uni WAIT_DONE_%=;\n\t"
        "bra.uni WAIT_LOOP_%=;\n\t"
        "WAIT_DONE_%=:\n\t"
        "}"
        :: "r"(mb) : "memory");
}

// One full 4096-pt FWHT + sign-scale + store for one row held in buf.
__device__ __forceinline__ void process_row(float* buf, float* dst,
                                            unsigned mask,
                                            int p1_base, int p2_base,
                                            int p3_base)
{
    float v[16];

    // P1: linear read; butterflies on i-bits {9..6}
    #pragma unroll
    for (int r = 0; r < 16; r++) v[r] = buf[p1_base + r * 64];
    #pragma unroll
    for (int m = 8; m >= 1; m >>= 1) {
        #pragma unroll
        for (int r = 0; r < 16; r++) {
            if ((r & m) == 0) {
                float a = v[r], b = v[r | m];
                v[r]     = a + b;
                v[r | m] = a - b;
            }
        }
    }
    __syncthreads();   // in-place reuse: all P1 reads done

    // T1: swizzled write (conflict-free)
    #pragma unroll
    for (int r = 0; r < 16; r++) buf[swz(p1_base + r * 64)] = v[r];
    __syncthreads();

    // P2: butterflies on i-bits {5..2}
    #pragma unroll
    for (int r = 0; r < 16; r++) v[r] = buf[swz(p2_base + r * 4)];
    #pragma unroll
    for (int m = 8; m >= 1; m >>= 1) {
        #pragma unroll
        for (int r = 0; r < 16; r++) {
            if ((r & m) == 0) {
                float a = v[r], b = v[r | m];
                v[r]     = a + b;
                v[r | m] = a - b;
            }
        }
    }
    #pragma unroll
    for (int r = 0; r < 16; r++) buf[swz(p2_base + r * 4)] = v[r];
    __syncthreads();

    // P3: LDS.128; butterflies on i-bits {11,10,1,0}
    #pragma unroll
    for (int c = 0; c < 4; c++) {
        float4 q = *(const float4*)(buf + swz(c * 1024 + p3_base));
        v[c * 4 + 0] = q.x;
        v[c * 4 + 1] = q.y;
        v[c * 4 + 2] = q.z;
        v[c * 4 + 3] = q.w;
    }
    #pragma unroll
    for (int m = 8; m >= 1; m >>= 1) {
        #pragma unroll
        for (int r = 0; r < 16; r++) {
            if ((r & m) == 0) {
                float a = v[r], b = v[r | m];
                v[r]     = a + b;
                v[r | m] = a - b;
            }
        }
    }

    // Epilogue: sign-XOR + exact 2^-6 scale, 4x STG.128
    #pragma unroll
    for (int c = 0; c < 4; c++) {
        float4 o;
        #pragma unroll
        for (int e = 0; e < 4; e++) {
            const int k = c * 4 + e;
            const unsigned sb = (mask >> k) << 31;
            ((float*)&o)[e] =
                __int_as_float(__float_as_int(v[k]) ^ (int)sb) * INV64;
        }
        *(float4*)(dst + c * 1024 + p3_base) = o;
    }
}

__global__ __launch_bounds__(THREADS)
void fwht_rotate_kernel(const float* __restrict__ w,
                        const float* __restrict__ x,
                        const float* __restrict__ rot,
                        float* __restrict__ out)
{
    __shared__ float bufA[DIM];
    __shared__ float bufB[DIM];
    __shared__ __align__(8) unsigned long long mbar[2];

    const int t    = threadIdx.x;
    const int lane = t & 31;
    const int warp = t >> 5;

    const int rowA = blockIdx.x;          // 0..6143  -> w rows
    const int rowB = rowA + GRID;         // 6144..12287

    const float* srcA = (rowA < W_ROWS)
        ? (w + (size_t)rowA * DIM)
        : (x + (size_t)(rowA - W_ROWS) * DIM);
    const float* srcB = (rowB < W_ROWS)
        ? (w + (size_t)rowB * DIM)
        : (x + (size_t)(rowB - W_ROWS) * DIM);

    const uint32_t mb0 = smem_u32(&mbar[0]);
    const uint32_t mb1 = smem_u32(&mbar[1]);

    // ---- Prologue: init both mbars, issue BOTH TMA bulk loads ----
    if (t == 0) {
        asm volatile("mbarrier.init.shared.b64 [%0], 1;" :: "r"(mb0) : "memory");
        asm volatile("mbarrier.init.shared.b64 [%0], 1;" :: "r"(mb1) : "memory");
        asm volatile("fence.proxy.async.shared::cta;" ::: "memory");
        asm volatile("mbarrier.arrive.expect_tx.shared.b64 _, [%0], %1;"
                     :: "r"(mb0), "r"((uint32_t)ROW_BYTES) : "memory");
        asm volatile("cp.async.bulk.shared::cta.global.mbarrier::complete_tx::bytes "
                     "[%0], [%1], %2, [%3];"
                     :: "r"(smem_u32(bufA)), "l"(srcA),
                        "r"((uint32_t)ROW_BYTES), "r"(mb0) : "memory");
        asm volatile("mbarrier.arrive.expect_tx.shared.b64 _, [%0], %1;"
                     :: "r"(mb1), "r"((uint32_t)ROW_BYTES) : "memory");
        asm volatile("cp.async.bulk.shared::cta.global.mbarrier::complete_tx::bytes "
                     "[%0], [%1], %2, [%3];"
                     :: "r"(smem_u32(bufB)), "l"(srcB),
                        "r"((uint32_t)ROW_BYTES), "r"(mb1) : "memory");
    }

    // ---- Pack per-thread sign mask from rot row 0 (overlaps TMA wait);
    //      amortized over BOTH rows ----
    const int p3_base = t * 4;
    unsigned mask = 0;
    #pragma unroll
    for (int c = 0; c < 4; c++) {
        float4 s = __ldg((const float4*)(rot + c * 1024 + p3_base));
        mask |= (__float_as_uint(s.x) >> 31) << (c * 4 + 0);
        mask |= (__float_as_uint(s.y) >> 31) << (c * 4 + 1);
        mask |= (__float_as_uint(s.z) >> 31) << (c * 4 + 2);
        mask |= (__float_as_uint(s.w) >> 31) << (c * 4 + 3);
    }

    const int p1_base = (t >> 6) * 1024 + (t & 63);
    const int p2_base = (warp * 8 + ((lane >> 2) & 7)) * 64 + (lane & 3);

    // ---- Barrier-init visibility, then row A (its TMA was issued first) ----
    __syncthreads();
    mbar_wait0(mb0);
    process_row(bufA, out + (size_t)rowA * DIM, mask,
                p1_base, p2_base, p3_base);

    // ---- Row B: load fully hidden behind row A's compute ----
    mbar_wait0(mb1);
    __syncthreads();   // keep warps phase-aligned entering row B
    process_row(bufB, out + (size_t)rowB * DIM, mask,
                p1_base, p2_base, p3_base);
}

extern "C" void kernel_launch(void* const* d_in, const int* in_sizes, int n_in,
                              void* d_out, int out_size)
{
    const float* w   = (const float*)d_in[0];   // [4096, 4096]
    const float* x   = (const float*)d_in[1];   // [4, 2048, 4096]
    const float* rot = (const float*)d_in[2];   // [4096, 4096]
    float* out = (float*)d_out;                 // w_rotated then a_rotated

    (void)in_sizes; (void)n_in; (void)out_size;

    fwht_rotate_kernel<<<GRID, THREADS>>>(w, x, rot, out);
}